// round 1
// baseline (speedup 1.0000x reference)
#include <cuda_runtime.h>
#include <math.h>

#define NND   50000
#define NE    800000
#define DIN   128
#define DH    64
#define DOUT  16
#define CAP   64          // max in-degree bin capacity; Poisson(16) tail @64 ~ 1e-20

// ---------------- scratch (static __device__ allocations only) ----------------
__device__ float g_h0[NND * DH];        // x @ W1
__device__ float g_a1[NND * DH];        // spmm(h0)
__device__ float g_t2[NND * DH];        // tanh(a1) @ W2
__device__ float g_a2[NND * DH];        // spmm(t2)
__device__ float g_t3[NND * DOUT];      // a2 @ W3
__device__ int   g_cnt[NND];            // per-dst degree / scatter cursor
__device__ int   g_slot_src[(size_t)NND * CAP];
__device__ float g_slot_val[(size_t)NND * CAP];

// ---------------- graph build ----------------
__global__ void zero_cnt_kernel() {
    int i = blockIdx.x * 256 + threadIdx.x;
    if (i < NND) g_cnt[i] = 0;
}

__global__ void scatter_kernel(const int* __restrict__ esrc,
                               const int* __restrict__ edst,
                               const float* __restrict__ eval) {
    int e = blockIdx.x * 256 + threadIdx.x;
    if (e >= NE) return;
    int d = edst[e];
    int pos = atomicAdd(&g_cnt[d], 1);
    if (pos < CAP) {
        size_t idx = (size_t)d * CAP + pos;
        g_slot_src[idx] = esrc[e];
        g_slot_val[idx] = eval[e];
    }
}

// ---------------- GEMM1: h0 = x @ W1   [N,128]x[128,64] ----------------
__global__ void gemm1_kernel(const float* __restrict__ x,
                             const float* __restrict__ W1) {
    __shared__ float Ws[DIN * DH];     // 32 KB
    __shared__ float xs[32][DIN];      // 16 KB
    int tid = threadIdx.x;             // 256 threads
    for (int i = tid; i < DIN * DH; i += 256) Ws[i] = W1[i];
    int row0 = blockIdx.x * 32;
    for (int i = tid; i < 32 * DIN; i += 256) {
        int r = i >> 7, k = i & (DIN - 1);
        int row = row0 + r;
        xs[r][k] = (row < NND) ? x[(size_t)row * DIN + k] : 0.f;
    }
    __syncthreads();
    int c = tid & 63;          // output column
    int rq = tid >> 6;         // row quarter: rows rq*8 .. rq*8+7
    float acc[8];
#pragma unroll
    for (int j = 0; j < 8; j++) acc[j] = 0.f;
    for (int k = 0; k < DIN; k++) {
        float w = Ws[k * DH + c];
#pragma unroll
        for (int j = 0; j < 8; j++) acc[j] += xs[rq * 8 + j][k] * w;
    }
#pragma unroll
    for (int j = 0; j < 8; j++) {
        int row = row0 + rq * 8 + j;
        if (row < NND) g_h0[(size_t)row * DH + c] = acc[j];
    }
}

// ---------------- GEMM2: t2 = tanh(a1) @ W2  [N,64]x[64,64] ----------------
__global__ void gemm2_kernel(const float* __restrict__ W2) {
    __shared__ float Ws[DH * DH];      // 16 KB
    __shared__ float hs[32][DH];       // 8 KB
    int tid = threadIdx.x;
    for (int i = tid; i < DH * DH; i += 256) Ws[i] = W2[i];
    int row0 = blockIdx.x * 32;
    for (int i = tid; i < 32 * DH; i += 256) {
        int r = i >> 6, k = i & (DH - 1);
        int row = row0 + r;
        hs[r][k] = (row < NND) ? tanhf(g_a1[(size_t)row * DH + k]) : 0.f;
    }
    __syncthreads();
    int c = tid & 63;
    int rq = tid >> 6;
    float acc[8];
#pragma unroll
    for (int j = 0; j < 8; j++) acc[j] = 0.f;
    for (int k = 0; k < DH; k++) {
        float w = Ws[k * DH + c];
#pragma unroll
        for (int j = 0; j < 8; j++) acc[j] += hs[rq * 8 + j][k] * w;
    }
#pragma unroll
    for (int j = 0; j < 8; j++) {
        int row = row0 + rq * 8 + j;
        if (row < NND) g_t2[(size_t)row * DH + c] = acc[j];
    }
}

// ---------------- GEMM3: t3 = a2 @ W3  [N,64]x[64,16] ----------------
__global__ void gemm3_kernel(const float* __restrict__ W3) {
    __shared__ float Ws[DH * DOUT];    // 4 KB
    __shared__ float hs[64][DH];       // 16 KB
    int tid = threadIdx.x;
    for (int i = tid; i < DH * DOUT; i += 256) Ws[i] = W3[i];
    int row0 = blockIdx.x * 64;
    for (int i = tid; i < 64 * DH; i += 256) {
        int r = i >> 6, k = i & (DH - 1);
        int row = row0 + r;
        hs[r][k] = (row < NND) ? g_a2[(size_t)row * DH + k] : 0.f;
    }
    __syncthreads();
    int c = tid & 15;          // 16 output columns
    int rq = tid >> 4;         // 16 row groups of 4 rows
    float acc[4] = {0.f, 0.f, 0.f, 0.f};
    for (int k = 0; k < DH; k++) {
        float w = Ws[k * DOUT + c];
#pragma unroll
        for (int j = 0; j < 4; j++) acc[j] += hs[rq * 4 + j][k] * w;
    }
#pragma unroll
    for (int j = 0; j < 4; j++) {
        int row = row0 + rq * 4 + j;
        if (row < NND) g_t3[(size_t)row * DOUT + c] = acc[j];
    }
}

// ---------------- SPMM (pull mode), 64-dim: one warp per dst node ----------------
// which = 0: g_h0 -> g_a1   ;   which = 1: g_t2 -> g_a2
__global__ void spmm64_kernel(int which) {
    int node = blockIdx.x * 8 + (threadIdx.x >> 5);
    int lane = threadIdx.x & 31;
    if (node >= NND) return;
    const float* __restrict__ hin = which ? g_t2 : g_h0;
    float* __restrict__ hout      = which ? g_a2 : g_a1;
    int deg = min(g_cnt[node], CAP);
    size_t base = (size_t)node * CAP;
    float2 acc = make_float2(0.f, 0.f);
    for (int c0 = 0; c0 < deg; c0 += 32) {
        int i = c0 + lane;
        int s = 0; float v = 0.f;
        if (i < deg) { s = g_slot_src[base + i]; v = g_slot_val[base + i]; }
        int m = min(32, deg - c0);
        for (int j = 0; j < m; j++) {
            int   sj = __shfl_sync(0xffffffffu, s, j);
            float vj = __shfl_sync(0xffffffffu, v, j);
            float2 y = *(const float2*)(hin + (size_t)sj * DH + lane * 2);
            acc.x = fmaf(vj, y.x, acc.x);
            acc.y = fmaf(vj, y.y, acc.y);
        }
    }
    *(float2*)(hout + (size_t)node * DH + lane * 2) = acc;
}

// ---------------- SPMM 16-dim + fused row softmax -> d_out ----------------
__global__ void spmm16_softmax_kernel(float* __restrict__ out) {
    int node = blockIdx.x * 8 + (threadIdx.x >> 5);
    int lane = threadIdx.x & 31;
    if (node >= NND) return;
    int deg = min(g_cnt[node], CAP);
    size_t base = (size_t)node * CAP;
    float acc = 0.f;
    for (int c0 = 0; c0 < deg; c0 += 32) {
        int i = c0 + lane;
        int s = 0; float v = 0.f;
        if (i < deg) { s = g_slot_src[base + i]; v = g_slot_val[base + i]; }
        int m = min(32, deg - c0);
        for (int j = 0; j < m; j++) {
            int   sj = __shfl_sync(0xffffffffu, s, j);
            float vj = __shfl_sync(0xffffffffu, v, j);
            if (lane < DOUT)
                acc = fmaf(vj, g_t3[(size_t)sj * DOUT + lane], acc);
        }
    }
    // softmax over the 16 values held in lanes 0..15 (lanes 16..31 inert)
    float xv = (lane < DOUT) ? acc : -INFINITY;
    float mx = xv;
#pragma unroll
    for (int o = 8; o > 0; o >>= 1)
        mx = fmaxf(mx, __shfl_xor_sync(0xffffffffu, mx, o));
    float e = (lane < DOUT) ? expf(xv - mx) : 0.f;
    float ssum = e;
#pragma unroll
    for (int o = 8; o > 0; o >>= 1)
        ssum += __shfl_xor_sync(0xffffffffu, ssum, o);
    if (lane < DOUT)
        out[(size_t)node * DOUT + lane] = e / ssum;
}

// ---------------- launch ----------------
extern "C" void kernel_launch(void* const* d_in, const int* in_sizes, int n_in,
                              void* d_out, int out_size) {
    const float* x    = (const float*)d_in[0];
    const int*   esrc = (const int*)  d_in[1];
    const int*   edst = (const int*)  d_in[2];
    const float* evals= (const float*)d_in[3];
    const float* W1   = (const float*)d_in[4];
    const float* W2   = (const float*)d_in[5];
    const float* W3   = (const float*)d_in[6];
    float* out = (float*)d_out;

    zero_cnt_kernel<<<(NND + 255) / 256, 256>>>();
    scatter_kernel<<<(NE + 255) / 256, 256>>>(esrc, edst, evals);
    gemm1_kernel<<<(NND + 31) / 32, 256>>>(x, W1);
    spmm64_kernel<<<(NND + 7) / 8, 256>>>(0);      // a1 = A @ h0
    gemm2_kernel<<<(NND + 31) / 32, 256>>>(W2);    // t2 = tanh(a1) @ W2
    spmm64_kernel<<<(NND + 7) / 8, 256>>>(1);      // a2 = A @ t2
    gemm3_kernel<<<(NND + 63) / 64, 256>>>(W3);    // t3 = a2 @ W3
    spmm16_softmax_kernel<<<(NND + 7) / 8, 256>>>(out);
}

// round 2
// speedup vs baseline: 1.5095x; 1.5095x over previous
#include <cuda_runtime.h>
#include <math.h>

#define NND   50000
#define NE    800000
#define DIN   128
#define DH    64
#define DOUT  16
#define CAP   64

// ---------------- packed f32x2 helpers (Blackwell packed fp32 pipe) ----------------
typedef unsigned long long ull;

__device__ __forceinline__ ull f2_pack2(float v) {
    ull r; asm("mov.b64 %0, {%1,%2};" : "=l"(r) : "f"(v), "f"(v)); return r;
}
__device__ __forceinline__ ull ffma2(ull a, ull b, ull c) {
    ull d; asm("fma.rn.f32x2 %0, %1, %2, %3;" : "=l"(d) : "l"(a), "l"(b), "l"(c)); return d;
}
__device__ __forceinline__ float2 f2_unpack(ull v) {
    float2 r; asm("mov.b64 {%0,%1}, %2;" : "=f"(r.x), "=f"(r.y) : "l"(v)); return r;
}

// ---------------- scratch ----------------
__device__ float g_h0[NND * DH];        // x @ W1
__device__ float g_t1[NND * DH];        // tanh(spmm(h0))   (tanh fused into spmm epilogue)
__device__ float g_t2[NND * DH];        // t1 @ W2
__device__ float g_a2[NND * DH];        // spmm(t2)
__device__ float g_t3[NND * DOUT];      // a2 @ W3
__device__ int   g_cnt[NND];
__device__ int2  g_slot[(size_t)NND * CAP];   // {src, float-bits of val}

// ---------------- graph build ----------------
__global__ void zero_cnt_kernel() {
    int i = blockIdx.x * 256 + threadIdx.x;
    if (i < NND) g_cnt[i] = 0;
}

__global__ void scatter_kernel(const int* __restrict__ esrc,
                               const int* __restrict__ edst,
                               const float* __restrict__ eval) {
    int e = blockIdx.x * 256 + threadIdx.x;
    if (e >= NE) return;
    int d = edst[e];
    int pos = atomicAdd(&g_cnt[d], 1);
    if (pos < CAP)
        g_slot[(size_t)d * CAP + pos] = make_int2(esrc[e], __float_as_int(eval[e]));
}

// ---------------- GEMM1: g_h0 = x @ W1   [N,128]x[128,64] ----------------
// 64-row tiles, transposed smem (row pairs contiguous), 8 rows x 2 cols per thread.
__global__ void gemm1_kernel(const float* __restrict__ x,
                             const float* __restrict__ W1) {
    __shared__ float xt[DIN * 66];     // transposed tile, pitch 66 (33.8 KB)
    int tid = threadIdx.x;
    int row0 = blockIdx.x * 64;
    for (int i = tid; i < 64 * (DIN / 4); i += 256) {
        int r = i >> 5, q = i & 31;
        int row = row0 + r;
        float4 v = (row < NND) ? *(const float4*)(x + (size_t)row * DIN + q * 4)
                               : make_float4(0.f, 0.f, 0.f, 0.f);
        xt[(q * 4 + 0) * 66 + r] = v.x;
        xt[(q * 4 + 1) * 66 + r] = v.y;
        xt[(q * 4 + 2) * 66 + r] = v.z;
        xt[(q * 4 + 3) * 66 + r] = v.w;
    }
    __syncthreads();
    int c0 = (tid & 31) * 2;          // 2 output columns
    int rg = tid >> 5;                // 8 row-groups of 8 rows
    ull acc[4][2] = {};
    const float* xb = xt + rg * 8;
    for (int k = 0; k < DIN; k++) {
        float2 w = *(const float2*)(W1 + k * DH + c0);   // L1-resident
        ull w0 = f2_pack2(w.x), w1 = f2_pack2(w.y);
        const float* xk = xb + k * 66;
#pragma unroll
        for (int p = 0; p < 4; p++) {
            ull xp = *(const ull*)(xk + p * 2);          // 2 rows, broadcast
            acc[p][0] = ffma2(xp, w0, acc[p][0]);
            acc[p][1] = ffma2(xp, w1, acc[p][1]);
        }
    }
#pragma unroll
    for (int p = 0; p < 4; p++) {
        float2 a0 = f2_unpack(acc[p][0]);
        float2 a1 = f2_unpack(acc[p][1]);
        int r0 = row0 + rg * 8 + p * 2;
        if (r0 < NND)     *(float2*)(g_h0 + (size_t)r0 * DH + c0)       = make_float2(a0.x, a1.x);
        if (r0 + 1 < NND) *(float2*)(g_h0 + (size_t)(r0 + 1) * DH + c0) = make_float2(a0.y, a1.y);
    }
}

// ---------------- GEMM2: g_t2 = g_t1 @ W2  [N,64]x[64,64] ----------------
__global__ void gemm2_kernel(const float* __restrict__ W2) {
    __shared__ float xt[DH * 66];      // 16.9 KB
    int tid = threadIdx.x;
    int row0 = blockIdx.x * 64;
    for (int i = tid; i < 64 * (DH / 4); i += 256) {
        int r = i >> 4, q = i & 15;
        int row = row0 + r;
        float4 v = (row < NND) ? *(const float4*)(g_t1 + (size_t)row * DH + q * 4)
                               : make_float4(0.f, 0.f, 0.f, 0.f);
        xt[(q * 4 + 0) * 66 + r] = v.x;
        xt[(q * 4 + 1) * 66 + r] = v.y;
        xt[(q * 4 + 2) * 66 + r] = v.z;
        xt[(q * 4 + 3) * 66 + r] = v.w;
    }
    __syncthreads();
    int c0 = (tid & 31) * 2;
    int rg = tid >> 5;
    ull acc[4][2] = {};
    const float* xb = xt + rg * 8;
    for (int k = 0; k < DH; k++) {
        float2 w = *(const float2*)(W2 + k * DH + c0);
        ull w0 = f2_pack2(w.x), w1 = f2_pack2(w.y);
        const float* xk = xb + k * 66;
#pragma unroll
        for (int p = 0; p < 4; p++) {
            ull xp = *(const ull*)(xk + p * 2);
            acc[p][0] = ffma2(xp, w0, acc[p][0]);
            acc[p][1] = ffma2(xp, w1, acc[p][1]);
        }
    }
#pragma unroll
    for (int p = 0; p < 4; p++) {
        float2 a0 = f2_unpack(acc[p][0]);
        float2 a1 = f2_unpack(acc[p][1]);
        int r0 = row0 + rg * 8 + p * 2;
        if (r0 < NND)     *(float2*)(g_t2 + (size_t)r0 * DH + c0)       = make_float2(a0.x, a1.x);
        if (r0 + 1 < NND) *(float2*)(g_t2 + (size_t)(r0 + 1) * DH + c0) = make_float2(a0.y, a1.y);
    }
}

// ---------------- GEMM3: g_t3 = g_a2 @ W3  [N,64]x[64,16] ----------------
__global__ void gemm3_kernel(const float* __restrict__ W3) {
    __shared__ float xt[DH * 66];      // 16.9 KB
    int tid = threadIdx.x;
    int row0 = blockIdx.x * 64;
    for (int i = tid; i < 64 * (DH / 4); i += 256) {
        int r = i >> 4, q = i & 15;
        int row = row0 + r;
        float4 v = (row < NND) ? *(const float4*)(g_a2 + (size_t)row * DH + q * 4)
                               : make_float4(0.f, 0.f, 0.f, 0.f);
        xt[(q * 4 + 0) * 66 + r] = v.x;
        xt[(q * 4 + 1) * 66 + r] = v.y;
        xt[(q * 4 + 2) * 66 + r] = v.z;
        xt[(q * 4 + 3) * 66 + r] = v.w;
    }
    __syncthreads();
    int c0 = (tid & 7) * 2;           // 16 cols -> 8 col-pairs
    int rg = tid >> 3;                // 32 row-groups of 2 rows
    ull acc0 = 0, acc1 = 0;
    const float* xb = xt + rg * 2;
    for (int k = 0; k < DH; k++) {
        float2 w = *(const float2*)(W3 + k * DOUT + c0);
        ull xp = *(const ull*)(xb + k * 66);
        acc0 = ffma2(xp, f2_pack2(w.x), acc0);
        acc1 = ffma2(xp, f2_pack2(w.y), acc1);
    }
    float2 a0 = f2_unpack(acc0);
    float2 a1 = f2_unpack(acc1);
    int r0 = row0 + rg * 2;
    if (r0 < NND)     *(float2*)(g_t3 + (size_t)r0 * DOUT + c0)       = make_float2(a0.x, a1.x);
    if (r0 + 1 < NND) *(float2*)(g_t3 + (size_t)(r0 + 1) * DOUT + c0) = make_float2(a0.y, a1.y);
}

// ---------------- SPMM 64-dim, pull mode: one warp per dst, smem-staged edges ----------------
// WHICH=0: g_h0 -> tanh -> g_t1 ;  WHICH=1: g_t2 -> g_a2
template <int WHICH>
__global__ void spmm64_kernel() {
    __shared__ int2 se[8][CAP];       // 4 KB
    int w = threadIdx.x >> 5, lane = threadIdx.x & 31;
    int node = blockIdx.x * 8 + w;
    if (node >= NND) return;
    const float* __restrict__ hin = WHICH ? g_t2 : g_h0;
    float* __restrict__ hout      = WHICH ? g_a2 : g_t1;
    int deg = min(g_cnt[node], CAP);
    size_t base = (size_t)node * CAP;
    for (int i = lane; i < deg; i += 32) se[w][i] = g_slot[base + i];
    __syncwarp();
    ull acc = 0;
#pragma unroll 4
    for (int j = 0; j < deg; j++) {
        int2 e = se[w][j];                                   // broadcast LDS.64
        ull y = *(const ull*)(hin + ((size_t)e.x << 6) + (lane << 1));  // gather LDG.64
        acc = ffma2(y, f2_pack2(__int_as_float(e.y)), acc);
    }
    float2 r = f2_unpack(acc);
    if (WHICH == 0) { r.x = tanhf(r.x); r.y = tanhf(r.y); }
    *(float2*)(hout + ((size_t)node << 6) + (lane << 1)) = r;
}

// ---------------- SPMM 16-dim + fused softmax: 2 edges per warp pass ----------------
__global__ void spmm16_softmax_kernel(float* __restrict__ out) {
    __shared__ int2 se[8][CAP];
    int w = threadIdx.x >> 5, lane = threadIdx.x & 31;
    int node = blockIdx.x * 8 + w;
    if (node >= NND) return;
    int deg = min(g_cnt[node], CAP);
    size_t base = (size_t)node * CAP;
    for (int i = lane; i < deg; i += 32) se[w][i] = g_slot[base + i];
    __syncwarp();
    int half = lane >> 4, dim = lane & 15;
    float acc = 0.f;
#pragma unroll 4
    for (int j = half; j < deg; j += 2) {
        int2 e = se[w][j];
        acc = fmaf(__int_as_float(e.y), g_t3[(size_t)e.x * DOUT + dim], acc);
    }
    acc += __shfl_down_sync(0xffffffffu, acc, 16);   // lanes 0..15 hold full sums
    float mx = acc;
#pragma unroll
    for (int o = 8; o > 0; o >>= 1)
        mx = fmaxf(mx, __shfl_xor_sync(0xffffffffu, mx, o));
    float e = expf(acc - mx);
    float s = e;
#pragma unroll
    for (int o = 8; o > 0; o >>= 1)
        s += __shfl_xor_sync(0xffffffffu, s, o);
    if (lane < DOUT)
        out[(size_t)node * DOUT + lane] = e / s;
}

// ---------------- launch ----------------
extern "C" void kernel_launch(void* const* d_in, const int* in_sizes, int n_in,
                              void* d_out, int out_size) {
    const float* x    = (const float*)d_in[0];
    const int*   esrc = (const int*)  d_in[1];
    const int*   edst = (const int*)  d_in[2];
    const float* evals= (const float*)d_in[3];
    const float* W1   = (const float*)d_in[4];
    const float* W2   = (const float*)d_in[5];
    const float* W3   = (const float*)d_in[6];
    float* out = (float*)d_out;

    zero_cnt_kernel<<<(NND + 255) / 256, 256>>>();
    scatter_kernel<<<(NE + 255) / 256, 256>>>(esrc, edst, evals);
    gemm1_kernel<<<(NND + 63) / 64, 256>>>(x, W1);
    spmm64_kernel<0><<<(NND + 7) / 8, 256>>>();     // t1 = tanh(A @ h0)
    gemm2_kernel<<<(NND + 63) / 64, 256>>>(W2);     // t2 = t1 @ W2
    spmm64_kernel<1><<<(NND + 7) / 8, 256>>>();     // a2 = A @ t2
    gemm3_kernel<<<(NND + 63) / 64, 256>>>(W3);     // t3 = a2 @ W3
    spmm16_softmax_kernel<<<(NND + 7) / 8, 256>>>(out);
}